// round 3
// baseline (speedup 1.0000x reference)
#include <cuda_runtime.h>
#include <math.h>

// Problem constants (fixed by the dataset)
#define E_NUM 32768
#define BATCH 128     // == H
#define DIM   1024    // IMG_DIM == TXT_DIM

// ---- device scratch (allocation-free: __device__ globals) ----
__device__ float g_imgT [DIM * BATCH];   // img^T  [i][b]
__device__ float g_txtT [DIM * BATCH];   // text^T [t][b]
__device__ float g_W1aT [BATCH * BATCH]; // W1[:, :128]^T  -> [b][j]
__device__ float g_W1bT [BATCH * BATCH]; // W1[:, 128:]^T  -> [b][j]
__device__ float g_UT   [DIM * BATCH];   // (W1a @ img + b1)^T : [s][j]
__device__ float g_VT   [DIM * BATCH];   // (W1b @ text)^T     : [t][j]

__device__ float g_a    [E_NUM];         // per-edge attention scalar
__device__ int   g_histS[DIM];           // out-degree of each src
__device__ int   g_histT[DIM];           // in-degree of each tgt
__device__ int   g_offS [DIM];           // exclusive prefix (CSR row starts)
__device__ int   g_offT [DIM];
__device__ int   g_curS [DIM];           // binning cursors (mutable copies)
__device__ int   g_curT [DIM];
__device__ uint2 g_csrS [E_NUM];         // grouped by src: {tgt, bits(a)}
__device__ uint2 g_csrT [E_NUM];         // grouped by tgt: {src, bits(a)}

// ---- fused transposes + histogram zeroing: one launch ----
// blocks [0,128):   img  [128 x 1024] -> g_imgT [1024 x 128]
// blocks [128,256): txt  [128 x 1024] -> g_txtT [1024 x 128]
// blocks [256,272): W1a  -> g_W1aT ;  [272,288): W1b -> g_W1bT
// block 288: zero g_histS/g_histT
__global__ void k_prep(const float* __restrict__ img, const float* __restrict__ txt,
                       const float* __restrict__ W1) {
    int id = blockIdx.x;
    if (id == 288) {
        int t = threadIdx.y * 32 + threadIdx.x;   // 0..1023
        g_histS[t] = 0;
        g_histT[t] = 0;
        return;
    }

    __shared__ float tile[32][33];
    const float* in;
    float* out;
    int in_stride, bx, by;
    if (id < 256) {
        bool isTxt = id >= 128;
        int lid = id & 127;
        in = (isTxt ? txt : img);
        out = isTxt ? g_txtT : g_imgT;
        in_stride = DIM;
        bx = lid & 31;
        by = lid >> 5;
    } else {
        bool isB = id >= 272;
        int lid = (id - 256) & 15;
        in = W1 + (isB ? BATCH : 0);
        out = isB ? g_W1bT : g_W1aT;
        in_stride = 2 * BATCH;
        bx = lid & 3;
        by = lid >> 2;
    }

    int x = bx * 32 + threadIdx.x;
    int y = by * 32 + threadIdx.y;
    tile[threadIdx.y][threadIdx.x] = in[(long)y * in_stride + x];
    __syncthreads();
    int ox = by * 32 + threadIdx.x;
    int oy = bx * 32 + threadIdx.y;
    out[(long)oy * BATCH + ox] = tile[threadIdx.x][threadIdx.y];
}

// ---- UT[s][j] = b1[j] + sum_b W1aT[b][j]*imgT[s][b]
//      VT[t][j] =         sum_b W1bT[b][j]*txtT[t][b]
__global__ void k_uv(const float* __restrict__ b1) {
    int  col = blockIdx.x & (DIM - 1);
    bool isV = blockIdx.x >= DIM;
    int  j   = threadIdx.x;

    const float* x  = (isV ? g_txtT : g_imgT) + col * BATCH;
    const float* Wt =  isV ? g_W1bT : g_W1aT;

    __shared__ float xs[BATCH];
    xs[j] = x[j];
    __syncthreads();

    float acc = isV ? 0.0f : b1[j];
#pragma unroll 16
    for (int b = 0; b < BATCH; ++b)
        acc = fmaf(Wt[b * BATCH + j], xs[b], acc);

    (isV ? g_VT : g_UT)[col * BATCH + j] = acc;
}

// ---- per-edge attention scalar + degree histograms ----
__global__ void k_a_hist(const int* __restrict__ src, const int* __restrict__ tgt,
                         const float* __restrict__ w2, const float* __restrict__ b2) {
    int warp = threadIdx.x >> 5;
    int lane = threadIdx.x & 31;
    int e    = blockIdx.x * 8 + warp;

    int s = src[e];
    int t = tgt[e];

    float4 u = reinterpret_cast<const float4*>(g_UT + s * BATCH)[lane];
    float4 v = reinterpret_cast<const float4*>(g_VT + t * BATCH)[lane];
    float4 w = reinterpret_cast<const float4*>(w2)[lane];

    float h0 = fmaxf(u.x + v.x, 0.0f);
    float h1 = fmaxf(u.y + v.y, 0.0f);
    float h2 = fmaxf(u.z + v.z, 0.0f);
    float h3 = fmaxf(u.w + v.w, 0.0f);

    float p = fmaf(h0, w.x, fmaf(h1, w.y, fmaf(h2, w.z, h3 * w.w)));
#pragma unroll
    for (int off = 16; off; off >>= 1)
        p += __shfl_xor_sync(0xffffffffu, p, off);

    if (lane == 0) {
        g_a[e] = 1.0f / (1.0f + __expf(-(p + b2[0])));
        atomicAdd(&g_histS[s], 1);
        atomicAdd(&g_histT[t], 1);
    }
}

// ---- exclusive prefix sums of both histograms (1 block, 1024 threads) ----
__global__ void k_scan() {
    __shared__ int sh[DIM];
    int tid = threadIdx.x;

    // src histogram
    int v = g_histS[tid];
    sh[tid] = v;
    __syncthreads();
#pragma unroll
    for (int d = 1; d < DIM; d <<= 1) {
        int t = (tid >= d) ? sh[tid - d] : 0;
        __syncthreads();
        sh[tid] += t;
        __syncthreads();
    }
    int excl = sh[tid] - v;
    g_offS[tid] = excl;
    g_curS[tid] = excl;
    __syncthreads();

    // tgt histogram
    v = g_histT[tid];
    sh[tid] = v;
    __syncthreads();
#pragma unroll
    for (int d = 1; d < DIM; d <<= 1) {
        int t = (tid >= d) ? sh[tid - d] : 0;
        __syncthreads();
        sh[tid] += t;
        __syncthreads();
    }
    excl = sh[tid] - v;
    g_offT[tid] = excl;
    g_curT[tid] = excl;
}

// ---- scatter edges into both CSR orderings ----
__global__ void k_bin(const int* __restrict__ src, const int* __restrict__ tgt) {
    int e = blockIdx.x * blockDim.x + threadIdx.x;
    int s = src[e];
    int t = tgt[e];
    unsigned abits = __float_as_uint(g_a[e]);

    int p = atomicAdd(&g_curS[s], 1);
    g_csrS[p] = make_uint2((unsigned)t, abits);
    int q = atomicAdd(&g_curT[t], 1);
    g_csrT[q] = make_uint2((unsigned)s, abits);
}

// ---- gather: each block computes 16 output rows of one side and writes the
// final [b][dim] layout directly (smem transpose). No atomics, single write.
// grid = (DIM/16, 2), block = 512 (4 warpgroups x 128, thread b = tid & 127)
__global__ void k_gather(float* __restrict__ out) {
    int side = blockIdx.y;                 // 0 = attended_img, 1 = attended_text
    int i0   = blockIdx.x * 16;
    int wg   = threadIdx.x >> 7;           // 0..3
    int b    = threadIdx.x & 127;

    const uint2* csr  = side ? g_csrT  : g_csrS;
    const int*   off  = side ? g_offT  : g_offS;
    const int*   cnt  = side ? g_histT : g_histS;
    const float* feat = side ? g_imgT  : g_txtT;

    __shared__ float sh[16][129];

#pragma unroll
    for (int rr = 0; rr < 4; ++rr) {
        int r = wg * 4 + rr;
        int i = i0 + r;
        int k0 = off[i];
        int n  = cnt[i];
        float acc = 0.0f;
        for (int k = 0; k < n; ++k) {
            uint2 pr = csr[k0 + k];
            acc = fmaf(__uint_as_float(pr.y), feat[pr.x * BATCH + b], acc);
        }
        sh[r][b] = acc;
    }
    __syncthreads();

    float* o = out + (size_t)side * BATCH * DIM;
#pragma unroll
    for (int it = 0; it < 4; ++it) {
        int idx = threadIdx.x + it * 512;
        int r  = idx & 15;
        int bb = idx >> 4;
        o[bb * DIM + i0 + r] = sh[r][bb];
    }
}

extern "C" void kernel_launch(void* const* d_in, const int* in_sizes, int n_in,
                              void* d_out, int out_size) {
    const float* img = (const float*)d_in[0];   // [128, 1024]
    const float* txt = (const float*)d_in[1];   // [128, 1024]
    const int*   src = (const int*)  d_in[2];   // [32768]
    const int*   tgt = (const int*)  d_in[3];   // [32768]
    const float* W1  = (const float*)d_in[4];   // [128, 256]
    const float* b1  = (const float*)d_in[5];   // [128]
    const float* w2  = (const float*)d_in[6];   // [128]
    const float* b2  = (const float*)d_in[7];   // [1]
    float* out = (float*)d_out;                 // [2 * 128 * 1024]

    dim3 tb(32, 32);

    // 1) transposes + histogram zeroing
    k_prep<<<289, tb>>>(img, txt, W1);

    // 2) U/V GEMMs
    k_uv<<<2 * DIM, BATCH>>>(b1);

    // 3) per-edge attention scalars + degree histograms
    k_a_hist<<<E_NUM / 8, 256>>>(src, tgt, w2, b2);

    // 4) prefix sums -> CSR row offsets + cursors
    k_scan<<<1, DIM>>>();

    // 5) bin edges into CSR order (both groupings)
    k_bin<<<E_NUM / 256, 256>>>(src, tgt);

    // 6) gather + direct output-layout write
    k_gather<<<dim3(DIM / 16, 2), 512>>>(out);
}

// round 4
// speedup vs baseline: 1.6338x; 1.6338x over previous
#include <cuda_runtime.h>
#include <math.h>

// Problem constants (fixed by the dataset)
#define E_NUM 32768
#define BATCH 128     // == H
#define DIM   1024    // IMG_DIM == TXT_DIM

// ---- device scratch (allocation-free: __device__ globals) ----
__device__ float g_imgT [DIM * BATCH];   // img^T  [i][b]
__device__ float g_txtT [DIM * BATCH];   // text^T [t][b]
__device__ float g_W1aT [BATCH * BATCH]; // W1[:, :128]^T  -> [b][j]
__device__ float g_W1bT [BATCH * BATCH]; // W1[:, 128:]^T  -> [b][j]
__device__ float g_UT   [DIM * BATCH];   // (W1a @ img + b1)^T : [s][j]
__device__ float g_VT   [DIM * BATCH];   // (W1b @ text)^T     : [t][j]
__device__ float g_oImgT[DIM * BATCH];   // attended_img^T [i][b]
__device__ float g_oTxtT[DIM * BATCH];   // attended_text^T [t][b]

// ---- fused transposes: one launch ----
// blocks [0,128):   img  [128 x 1024] -> g_imgT [1024 x 128]
// blocks [128,256): txt  [128 x 1024] -> g_txtT [1024 x 128]
// blocks [256,272): W1a -> g_W1aT ;  [272,288): W1b -> g_W1bT
__global__ void k_prep(const float* __restrict__ img, const float* __restrict__ txt,
                       const float* __restrict__ W1) {
    __shared__ float tile[32][33];
    int id = blockIdx.x;

    const float* in;
    float* out;
    int in_stride, bx, by;
    if (id < 256) {
        bool isTxt = id >= 128;
        int lid = id & 127;
        in = (isTxt ? txt : img);
        out = isTxt ? g_txtT : g_imgT;
        in_stride = DIM;
        bx = lid & 31;
        by = lid >> 5;
    } else {
        bool isB = id >= 272;
        int lid = (id - 256) & 15;
        in = W1 + (isB ? BATCH : 0);
        out = isB ? g_W1bT : g_W1aT;
        in_stride = 2 * BATCH;
        bx = lid & 3;
        by = lid >> 2;
    }

    int x = bx * 32 + threadIdx.x;
    int y = by * 32 + threadIdx.y;
    tile[threadIdx.y][threadIdx.x] = in[(long)y * in_stride + x];
    __syncthreads();
    int ox = by * 32 + threadIdx.x;
    int oy = bx * 32 + threadIdx.y;
    out[(long)oy * BATCH + ox] = tile[threadIdx.x][threadIdx.y];
}

// ---- U/V GEMM, register-blocked: 16 output columns per block ----
// UT[c][j] = b1[j] + sum_b W1aT[b][j] * imgT[c][b]   (blocks 0..63)
// VT[c][j] =         sum_b W1bT[b][j] * txtT[c][b]   (blocks 64..127)
// Also zeroes the scatter accumulators (same index space).
__global__ void k_uv(const float* __restrict__ b1) {
    int  blk = blockIdx.x;
    bool isV = blk >= 64;
    int  c0  = (blk & 63) * 16;
    int  j   = threadIdx.x;

    // fused zeroing of the scatter accumulators: 16 rows x 128 floats per block
    {
        float4 z = make_float4(0.f, 0.f, 0.f, 0.f);
        float4* zp = (float4*)((isV ? g_oTxtT : g_oImgT) + c0 * BATCH);
#pragma unroll
        for (int it = 0; it < 4; ++it)
            zp[threadIdx.x + it * 128] = z;
    }

    const float* x  = (isV ? g_txtT : g_imgT) + c0 * BATCH;
    const float* Wt =  isV ? g_W1bT : g_W1aT;

    __shared__ float xs[16][BATCH];
    {
        const float4* xv = (const float4*)x;
        float4* sv = (float4*)xs;
#pragma unroll
        for (int it = 0; it < 4; ++it)
            sv[threadIdx.x + it * 128] = xv[threadIdx.x + it * 128];
    }
    __syncthreads();

    float bias = isV ? 0.0f : b1[j];
    float acc[16];
#pragma unroll
    for (int c = 0; c < 16; ++c) acc[c] = bias;

#pragma unroll 8
    for (int b = 0; b < BATCH; ++b) {
        float w = Wt[b * BATCH + j];
#pragma unroll
        for (int c = 0; c < 16; ++c)
            acc[c] = fmaf(w, xs[c][b], acc[c]);
    }

    float* o = (isV ? g_VT : g_UT) + c0 * BATCH + j;
#pragma unroll
    for (int c = 0; c < 16; ++c)
        o[c * BATCH] = acc[c];
}

// ---- per-edge: a = sigmoid(w2 . relu(UT[s] + VT[t]) + b2), then scatter:
//      oImgT[s][:] += a * txtT[t][:];  oTxtT[t][:] += a * imgT[s][:]
// One warp per edge, float4 per lane, vectorized red.global.v4.f32.add.
__global__ void k_edge(const int* __restrict__ src, const int* __restrict__ tgt,
                       const float* __restrict__ w2, const float* __restrict__ b2) {
    int warp = threadIdx.x >> 5;
    int lane = threadIdx.x & 31;
    int e    = blockIdx.x * 8 + warp;

    int s = src[e];
    int t = tgt[e];

    float4 u = reinterpret_cast<const float4*>(g_UT + s * BATCH)[lane];
    float4 v = reinterpret_cast<const float4*>(g_VT + t * BATCH)[lane];
    float4 w = reinterpret_cast<const float4*>(w2)[lane];

    float h0 = fmaxf(u.x + v.x, 0.0f);
    float h1 = fmaxf(u.y + v.y, 0.0f);
    float h2 = fmaxf(u.z + v.z, 0.0f);
    float h3 = fmaxf(u.w + v.w, 0.0f);

    float p = fmaf(h0, w.x, fmaf(h1, w.y, fmaf(h2, w.z, h3 * w.w)));
#pragma unroll
    for (int off = 16; off; off >>= 1)
        p += __shfl_xor_sync(0xffffffffu, p, off);

    float a = 1.0f / (1.0f + __expf(-(p + b2[0])));

    float4 tx = reinterpret_cast<const float4*>(g_txtT + t * BATCH)[lane];
    float4 im = reinterpret_cast<const float4*>(g_imgT + s * BATCH)[lane];

    float* oi = g_oImgT + s * BATCH + lane * 4;
    float* ot = g_oTxtT + t * BATCH + lane * 4;

    asm volatile("red.global.v4.f32.add [%0], {%1, %2, %3, %4};"
                 :: "l"(oi), "f"(a * tx.x), "f"(a * tx.y), "f"(a * tx.z), "f"(a * tx.w)
                 : "memory");
    asm volatile("red.global.v4.f32.add [%0], {%1, %2, %3, %4};"
                 :: "l"(ot), "f"(a * im.x), "f"(a * im.y), "f"(a * im.z), "f"(a * im.w)
                 : "memory");
}

// ---- vectorized final transpose: 32 rows (i) x 128 cols (b) per block ----
// grid (DIM/32, 2), block 256. float4 loads, coalesced scalar stores.
__global__ void k_writeout(float* __restrict__ out) {
    int side = blockIdx.y;
    int i0   = blockIdx.x * 32;
    const float* in = side ? g_oTxtT : g_oImgT;
    float* o = out + (size_t)side * BATCH * DIM;

    __shared__ float4 tile4[32][33];   // [r][b/4], padded

    int warp = threadIdx.x >> 5;
    int lane = threadIdx.x & 31;
#pragma unroll
    for (int k = 0; k < 4; ++k) {
        int r = warp * 4 + k;
        tile4[r][lane] = reinterpret_cast<const float4*>(in + (i0 + r) * BATCH)[lane];
    }
    __syncthreads();

    const float* tf = (const float*)tile4;   // element (r,b) at tf[r*132 + b]
#pragma unroll
    for (int it = 0; it < 16; ++it) {
        int gid = threadIdx.x + it * 256;
        int r = gid & 31;
        int b = gid >> 5;
        o[b * DIM + i0 + r] = tf[r * 132 + b];
    }
}

extern "C" void kernel_launch(void* const* d_in, const int* in_sizes, int n_in,
                              void* d_out, int out_size) {
    const float* img = (const float*)d_in[0];   // [128, 1024]
    const float* txt = (const float*)d_in[1];   // [128, 1024]
    const int*   src = (const int*)  d_in[2];   // [32768]
    const int*   tgt = (const int*)  d_in[3];   // [32768]
    const float* W1  = (const float*)d_in[4];   // [128, 256]
    const float* b1  = (const float*)d_in[5];   // [128]
    const float* w2  = (const float*)d_in[6];   // [128]
    const float* b2  = (const float*)d_in[7];   // [1]
    float* out = (float*)d_out;                 // [2 * 128 * 1024]

    dim3 tb(32, 32);

    // 1) fused transposes
    k_prep<<<288, tb>>>(img, txt, W1);

    // 2) U/V GEMMs (register-blocked) + accumulator zeroing
    k_uv<<<128, BATCH>>>(b1);

    // 3) per-edge MLP + vectorized scatter-accumulate
    k_edge<<<E_NUM / 8, 256>>>(src, tgt, w2, b2);

    // 4) vectorized transpose into the output layout
    k_writeout<<<dim3(DIM / 32, 2), 256>>>(out);
}